// round 17
// baseline (speedup 1.0000x reference)
#include <cuda_runtime.h>
#include <cuda_fp16.h>
#include <cuda_bf16.h>
#include <cstdint>

#define BSZ 8192
#define DIM 256

// ---------------- device globals ----------------
__device__ float g_M[2][DIM * DIM];   // [0]=txt^T txt, [1]=img^T img (fp32)
__device__ float g_T[2][DIM];         // [0]=sum txt_j, [1]=sum img_j
__device__ float g_s[2][BSZ];         // N + lin + 0.5*quad per row (seeded with N)
__device__ __align__(256) __nv_bfloat16 g_b[2][BSZ * DIM];   // [0]=img, [1]=txt (bf16)

// ---------------- asm helpers (proven in prior passing rounds) ----------------
__device__ __forceinline__ void cp_async16(uint32_t saddr, const void* gsrc) {
    asm volatile("cp.async.cg.shared.global [%0], [%1], 16;\n" :: "r"(saddr), "l"(gsrc));
}
__device__ __forceinline__ void ldsm4(uint32_t addr, uint32_t& r0, uint32_t& r1,
                                      uint32_t& r2, uint32_t& r3) {
    asm volatile("ldmatrix.sync.aligned.m8n8.x4.shared.b16 {%0,%1,%2,%3}, [%4];"
                 : "=r"(r0), "=r"(r1), "=r"(r2), "=r"(r3) : "r"(addr));
}
__device__ __forceinline__ void ldsm4t(uint32_t addr, uint32_t& r0, uint32_t& r1,
                                       uint32_t& r2, uint32_t& r3) {
    asm volatile("ldmatrix.sync.aligned.m8n8.x4.trans.shared.b16 {%0,%1,%2,%3}, [%4];"
                 : "=r"(r0), "=r"(r1), "=r"(r2), "=r"(r3) : "r"(addr));
}
__device__ __forceinline__ void mma_bf16(float c[4], const uint32_t a[4],
                                         uint32_t b0, uint32_t b1) {
    asm volatile(
        "mma.sync.aligned.m16n8k16.row.col.f32.bf16.bf16.f32 "
        "{%0,%1,%2,%3}, {%4,%5,%6,%7}, {%8,%9}, {%0,%1,%2,%3};\n"
        : "+f"(c[0]), "+f"(c[1]), "+f"(c[2]), "+f"(c[3])
        : "r"(a[0]), "r"(a[1]), "r"(a[2]), "r"(a[3]), "r"(b0), "r"(b1));
}

#define MSP 264          // smem row stride in bf16 halves (256 + 8 pad)
#define MSPB (MSP * 2)   // bytes

// ---------------- init + cvt: zero M/T, seed s & out, fp32 -> bf16 ----------------
__global__ void init_cvt_kernel(const float* __restrict__ img, const float* __restrict__ txt,
                                float* __restrict__ out) {
    int i = blockIdx.x * blockDim.x + threadIdx.x;   // 524288 threads
    if (i < BSZ * DIM / 4) {
        float4 v = reinterpret_cast<const float4*>(img)[i];
        __nv_bfloat162* d = reinterpret_cast<__nv_bfloat162*>(g_b[0]) + 2 * i;
        d[0] = __floats2bfloat162_rn(v.x, v.y);
        d[1] = __floats2bfloat162_rn(v.z, v.w);
        v = reinterpret_cast<const float4*>(txt)[i];
        d = reinterpret_cast<__nv_bfloat162*>(g_b[1]) + 2 * i;
        d[0] = __floats2bfloat162_rn(v.x, v.y);
        d[1] = __floats2bfloat162_rn(v.z, v.w);
    }
    if (i < 2 * DIM * DIM) reinterpret_cast<float*>(g_M)[i] = 0.0f;
    if (i < 2 * DIM)       reinterpret_cast<float*>(g_T)[i] = 0.0f;
    if (i < 2 * BSZ)       reinterpret_cast<float*>(g_s)[i] = (float)BSZ;
    if (i == 0)            out[0] = logf((float)BSZ + 1.0f);
}

// ---------------- moments v2: M[c] = X^T X via output-stripe x split-K ----------------
// grid (4 col-tiles, 8 k-splits, 2 chains) = 64 CTAs. CTA streams 8 slabs of 128
// samples (cp.async double-buffered bf16), accumulates its 256x64 stripe in regs
// (warp w = rows [32w,32w+32), all 64 cols), flushes ONCE with atomics.
// Fragment/output mappings byte-identical to the proven R13-R15 moments kernel.
#define MOM_SMEM (2 * 128 * MSPB)   // 135168

__global__ __launch_bounds__(256) void moments_kernel() {
    extern __shared__ __nv_bfloat16 sx[];
    const int ct = blockIdx.x;        // col tile 0..3
    const int ks = blockIdx.y;        // k split 0..7
    const int c  = blockIdx.z;        // chain
    const __nv_bfloat16* src = c ? g_b[0] : g_b[1];
    const int j0 = ks * 1024;
    const int t = threadIdx.x, lane = t & 31, w = t >> 5;
    const uint32_t sbase = (uint32_t)__cvta_generic_to_shared(sx);

    auto load_slab = [&](int s) {
        const uint32_t dst = sbase + (uint32_t)((s & 1) * 128 * MSPB);
        const __nv_bfloat16* sp = src + (size_t)(j0 + s * 128) * DIM;
        #pragma unroll
        for (int j = 0; j < 16; j++) {
            int u = t + 256 * j;            // 0..4095
            int r = u >> 5, c16 = u & 31;
            cp_async16(dst + (uint32_t)(r * MSPB + c16 * 16),
                       sp + (size_t)r * DIM + c16 * 8);
        }
        asm volatile("cp.async.commit_group;\n");
    };

    load_slab(0);

    const int rowpart = (lane & 7) + ((lane >> 4) << 3);
    const uint32_t colpart = (uint32_t)(((lane >> 3) & 1) * 16);

    float acc[2][8][4] = {};
    float tsum = 0.0f;

    for (int s = 0; s < 8; s++) {
        if (s + 1 < 8) {
            load_slab(s + 1);
            asm volatile("cp.async.wait_group 1;\n");
        } else {
            asm volatile("cp.async.wait_group 0;\n");
        }
        __syncthreads();

        const uint32_t base = sbase + (uint32_t)((s & 1) * 128 * MSPB);

        if (ct == 0) {   // column sums (thread t = column t)
            const __nv_bfloat16* bb = sx + (s & 1) * 128 * MSP;
            #pragma unroll 16
            for (int r = 0; r < 128; r++) tsum += __bfloat162float(bb[r * MSP + t]);
        }

        #pragma unroll
        for (int kk = 0; kk < 8; kk++) {
            const uint32_t krow = base + (uint32_t)((16 * kk + rowpart) * MSPB) + colpart;
            uint32_t a[2][4], b[8][2];
            #pragma unroll
            for (int mi = 0; mi < 2; mi++)
                ldsm4t(krow + (uint32_t)((w * 32 + mi * 16) * 2),
                       a[mi][0], a[mi][1], a[mi][2], a[mi][3]);
            #pragma unroll
            for (int nq = 0; nq < 2; nq++) {
                uint32_t addr = krow + (uint32_t)((ct * 64 + nq * 32) * 2);
                uint32_t q0, q1, q2, q3;
                ldsm4t(addr, q0, q1, q2, q3);
                b[nq * 4 + 0][0] = q0; b[nq * 4 + 0][1] = q2;
                b[nq * 4 + 1][0] = q1; b[nq * 4 + 1][1] = q3;
                ldsm4t(addr + 32, q0, q1, q2, q3);
                b[nq * 4 + 2][0] = q0; b[nq * 4 + 2][1] = q2;
                b[nq * 4 + 3][0] = q1; b[nq * 4 + 3][1] = q3;
            }
            #pragma unroll
            for (int mi = 0; mi < 2; mi++)
                #pragma unroll
                for (int nf = 0; nf < 8; nf++)
                    mma_bf16(acc[mi][nf], a[mi], b[nf][0], b[nf][1]);
        }
        __syncthreads();
    }

    if (ct == 0) atomicAdd(&g_T[c][t], tsum);

    // single register flush (atomic across the 8 k-split CTAs)
    const int ra = w * 32 + (lane >> 2);
    #pragma unroll
    for (int mi = 0; mi < 2; mi++) {
        int r0 = ra + mi * 16;
        #pragma unroll
        for (int nf = 0; nf < 8; nf++) {
            int cb = ct * 64 + nf * 8 + 2 * (lane & 3);
            atomicAdd(&g_M[c][r0 * DIM + cb],           acc[mi][nf][0]);
            atomicAdd(&g_M[c][r0 * DIM + cb + 1],       acc[mi][nf][1]);
            atomicAdd(&g_M[c][(r0 + 8) * DIM + cb],     acc[mi][nf][2]);
            atomicAdd(&g_M[c][(r0 + 8) * DIM + cb + 1], acc[mi][nf][3]);
        }
    }
}

// ---------------- quad+lin: s[chain][i] += x_i.T + 0.5 x_i^T M x_i (proven, 45.8us run) --
#define QUAD_SMEM ((128 + 256) * MSPB)

__global__ __launch_bounds__(256, 1) void quad_kernel(const float* __restrict__ img,
                                                      const float* __restrict__ txt) {
    extern __shared__ __nv_bfloat16 smq[];
    __shared__ float sT[DIM];
    __nv_bfloat16* sA = smq;
    __nv_bfloat16* sM = smq + 128 * MSP;
    const int chain = blockIdx.y;
    const float* Asrc = chain ? txt : img;
    const float* Msrc = g_M[chain];
    const int m0g = blockIdx.x * 128;
    const int t = threadIdx.x, lane = t & 31, warp = t >> 5;
    const int wm = warp & 3, wn = warp >> 2;

    if (t < DIM) sT[t] = g_T[chain][t];
    for (int idx = t; idx < 128 * 64; idx += 256) {
        int r = idx >> 6, c4 = idx & 63;
        float4 v = *reinterpret_cast<const float4*>(Asrc + (size_t)(m0g + r) * DIM + c4 * 4);
        __nv_bfloat162* d = reinterpret_cast<__nv_bfloat162*>(sA + r * MSP + c4 * 4);
        d[0] = __floats2bfloat162_rn(v.x, v.y);
        d[1] = __floats2bfloat162_rn(v.z, v.w);
    }
    for (int idx = t; idx < 256 * 64; idx += 256) {
        int r = idx >> 6, c4 = idx & 63;
        float4 v = *reinterpret_cast<const float4*>(Msrc + r * DIM + c4 * 4);
        __nv_bfloat162* d = reinterpret_cast<__nv_bfloat162*>(sM + r * MSP + c4 * 4);
        d[0] = __floats2bfloat162_rn(v.x, v.y);
        d[1] = __floats2bfloat162_rn(v.z, v.w);
    }
    __syncthreads();

    const uint32_t sAb = (uint32_t)__cvta_generic_to_shared(sA);
    const uint32_t sMb = (uint32_t)__cvta_generic_to_shared(sM);
    const int lrow = lane & 15;
    const int lk = (lane >> 4) * 8;

    float qp[4] = {0.f, 0.f, 0.f, 0.f};

    for (int nt = 0; nt < 4; nt++) {
        float cacc[2][4][4] = {};
        #pragma unroll
        for (int ks = 0; ks < 16; ks++) {
            const int k0 = ks * 16;
            uint32_t a[2][4], b[4][2];
            #pragma unroll
            for (int mi = 0; mi < 2; mi++) {
                int rb = wm * 32 + mi * 16;
                ldsm4(sAb + (uint32_t)(((rb + lrow) * MSP + k0 + lk) * 2),
                      a[mi][0], a[mi][1], a[mi][2], a[mi][3]);
            }
            #pragma unroll
            for (int g16 = 0; g16 < 2; g16++) {
                int nbq = nt * 64 + wn * 32 + g16 * 16;
                uint32_t q0, q1, q2, q3;
                ldsm4(sMb + (uint32_t)(((nbq + lrow) * MSP + k0 + lk) * 2), q0, q1, q2, q3);
                b[g16 * 2][0] = q0;     b[g16 * 2][1] = q2;
                b[g16 * 2 + 1][0] = q1; b[g16 * 2 + 1][1] = q3;
            }
            #pragma unroll
            for (int mi = 0; mi < 2; mi++)
                #pragma unroll
                for (int ni = 0; ni < 4; ni++)
                    mma_bf16(cacc[mi][ni], a[mi], b[ni][0], b[ni][1]);
        }
        #pragma unroll
        for (int mi = 0; mi < 2; mi++) {
            int r0 = wm * 32 + mi * 16 + (lane >> 2);
            #pragma unroll
            for (int ni = 0; ni < 4; ni++) {
                int col = nt * 64 + wn * 32 + ni * 8 + 2 * (lane & 3);
                float t0 = sT[col], t1 = sT[col + 1];
                float x0 = __bfloat162float(sA[r0 * MSP + col]);
                float x1 = __bfloat162float(sA[r0 * MSP + col + 1]);
                float x2 = __bfloat162float(sA[(r0 + 8) * MSP + col]);
                float x3 = __bfloat162float(sA[(r0 + 8) * MSP + col + 1]);
                qp[mi * 2]     += x0 * (t0 + 0.5f * cacc[mi][ni][0])
                                + x1 * (t1 + 0.5f * cacc[mi][ni][1]);
                qp[mi * 2 + 1] += x2 * (t0 + 0.5f * cacc[mi][ni][2])
                                + x3 * (t1 + 0.5f * cacc[mi][ni][3]);
            }
        }
    }
    #pragma unroll
    for (int j = 0; j < 4; j++) {
        qp[j] += __shfl_xor_sync(0xffffffffu, qp[j], 1);
        qp[j] += __shfl_xor_sync(0xffffffffu, qp[j], 2);
    }
    if ((lane & 3) == 0) {
        int rbase = m0g + wm * 32 + (lane >> 2);
        atomicAdd(&g_s[chain][rbase],      qp[0]);
        atomicAdd(&g_s[chain][rbase + 8],  qp[1]);
        atomicAdd(&g_s[chain][rbase + 16], qp[2]);
        atomicAdd(&g_s[chain][rbase + 24], qp[3]);
    }
}

// ---------------- finalize (proven 45.8us version): warp per row, both chains ----------
__global__ void finalize_kernel(const float* __restrict__ img, const float* __restrict__ txt,
                                const int* __restrict__ labels, float* __restrict__ out) {
    __shared__ float sred[8];
    int gw = (blockIdx.x * blockDim.x + threadIdx.x) >> 5;
    int lane = threadIdx.x & 31, w = threadIdx.x >> 5;
    const int i = gw;
    const int l = labels[i];

    float d1 = 0.f, d2 = 0.f;
    #pragma unroll
    for (int u = 0; u < 2; u++) {
        int o = lane * 2 + u;
        float4 vi = reinterpret_cast<const float4*>(img + (size_t)i * DIM)[o];
        float4 vt = reinterpret_cast<const float4*>(txt + (size_t)i * DIM)[o];
        float4 wl = reinterpret_cast<const float4*>(txt + (size_t)l * DIM)[o];
        float4 ul = reinterpret_cast<const float4*>(img + (size_t)l * DIM)[o];
        d1 += vi.x * wl.x + vi.y * wl.y + vi.z * wl.z + vi.w * wl.w;
        d2 += vt.x * ul.x + vt.y * ul.y + vt.z * ul.z + vt.w * ul.w;
    }
    #pragma unroll
    for (int off = 16; off > 0; off >>= 1) {
        d1 += __shfl_xor_sync(0xffffffffu, d1, off);
        d2 += __shfl_xor_sync(0xffffffffu, d2, off);
    }
    if (lane == 0) {
        float p1 = __expf(d1) / g_s[0][i];
        float p2 = __expf(d2) / g_s[1][i];
        sred[w] = p1 + p2;
    }
    __syncthreads();
    if (threadIdx.x == 0) {
        float s = 0.0f;
        #pragma unroll
        for (int j = 0; j < 8; j++) s += sred[j];
        atomicAdd(out, -s * (0.5f / (float)BSZ));
    }
}

// ---------------- launch ----------------
extern "C" void kernel_launch(void* const* d_in, const int* in_sizes, int n_in,
                              void* d_out, int out_size) {
    const float* img    = (const float*)d_in[0];
    const float* txt    = (const float*)d_in[1];
    const int*   labels = (const int*)d_in[2];
    float* out = (float*)d_out;
    (void)in_sizes; (void)n_in; (void)out_size;

    cudaFuncSetAttribute(moments_kernel, cudaFuncAttributeMaxDynamicSharedMemorySize, MOM_SMEM);
    cudaFuncSetAttribute(quad_kernel,    cudaFuncAttributeMaxDynamicSharedMemorySize, QUAD_SMEM);

    init_cvt_kernel<<<BSZ * DIM / 4 / 256, 256>>>(img, txt, out);  // cvt + zero/seed

    dim3 mgrid(4, 8, 2);                                           // 64 CTAs
    moments_kernel<<<mgrid, 256, MOM_SMEM>>>();                    // M = X^T X, T

    dim3 qgrid(BSZ / 128, 2);                                      // (64, 2)
    quad_kernel<<<qgrid, 256, QUAD_SMEM>>>(img, txt);              // s += lin + 0.5*quad

    finalize_kernel<<<BSZ / 8, 256>>>(img, txt, labels, out);      // gathers + loss
}